// round 6
// baseline (speedup 1.0000x reference)
#include <cuda_runtime.h>
#include <cuda_fp16.h>
#include <cstdint>

// ---------------------------------------------------------------------------
// FNO on sm_103a, fp16 HMMA (m16n8k16) + swizzled-weight cp.async pipeline.
//   h0 = relu(mu @ W1 + b1)
//   h  = relu(h @ B_l + x-term_l)   l=0..3  (circulant form of rfft*fw->irfft)
//   out = h @ W2 + b2
// Weights pre-packed in global EXACTLY as the smem image (XOR-swizzled 128B
// rows, 32KB per 64-K chunk) -> linear cp.async, conflict-free ldmatrix.
// 256 threads, 64 rows/CTA, 104KB SMEM -> 2 CTAs/SM.
// Single-barrier chunk pipeline: wait(prev copy) -> bar -> prefetch(next) ->
// gemm(cur); cp.async of chunk id+1 overlaps gemm of chunk id.
// ---------------------------------------------------------------------------

#define NMODES 256
#define NLAYERS 4
#define MROWS 64
#define NTHREADS 256
#define HW 132                        // h row stride in 32-bit words
#define H_BYTES (MROWS * HW * 4)      // 33792
#define WBUF_BYTES (NMODES * 128)     // 32768 (swizzled, no pad)
#define WBUF0_OFF H_BYTES
#define WBUF1_OFF (WBUF0_OFF + WBUF_BYTES)
#define G_OFF  (WBUF1_OFF + WBUF_BYTES)      // 99328
#define X_OFF  (G_OFF + 5 * NMODES * 4)      // 104448
#define W2_OFF (X_OFF + MROWS * 4 * 4)       // 105472
#define SMEM_TOTAL (W2_OFF + NMODES * 4)     // 106496 = 104KB
#define FH_STRIDE 260                 // final fp32 h row stride (floats)
#define NCHUNKS (1 + NLAYERS * 4)     // 17

__device__ float g_dev[NLAYERS * NMODES];
// packed weight image: [chunk][n][64 halves], row pre-swizzled so that the
// 16B segment at position p holds source k-segment (p ^ (n&7)).
__device__ __align__(16) __half w_sw[NCHUNKS * NMODES * 64];

__device__ __forceinline__ uint32_t smem_u32(const void* p) {
    uint32_t a;
    asm("{ .reg .u64 t; cvta.to.shared.u64 t, %1; cvt.u32.u64 %0, t; }" : "=r"(a) : "l"(p));
    return a;
}

#define CP_ASYNC16(dst, src) \
    asm volatile("cp.async.cg.shared.global [%0], [%1], 16;" :: "r"(dst), "l"(src) : "memory")
#define CP_COMMIT() asm volatile("cp.async.commit_group;" ::: "memory")
#define CP_WAIT(n)  asm volatile("cp.async.wait_group %0;" :: "n"(n) : "memory")

__device__ __forceinline__ void mma16(float* c, const uint32_t* a, uint32_t b0, uint32_t b1) {
    asm volatile(
        "mma.sync.aligned.m16n8k16.row.col.f32.f16.f16.f32 "
        "{%0,%1,%2,%3}, {%4,%5,%6,%7}, {%8,%9}, {%0,%1,%2,%3};\n"
        : "+f"(c[0]), "+f"(c[1]), "+f"(c[2]), "+f"(c[3])
        : "r"(a[0]), "r"(a[1]), "r"(a[2]), "r"(a[3]), "r"(b0), "r"(b1));
}

__device__ __forceinline__ void ldsm_x4(uint32_t& r0, uint32_t& r1, uint32_t& r2, uint32_t& r3,
                                        uint32_t addr) {
    asm volatile("ldmatrix.sync.aligned.m8n8.x4.shared.b16 {%0,%1,%2,%3}, [%4];"
                 : "=r"(r0), "=r"(r1), "=r"(r2), "=r"(r3) : "r"(addr));
}

// ---------------- preludes ----------------
__global__ void build_g(const float* __restrict__ fw) {
    int l = blockIdx.x, n = threadIdx.x;
    const float* f = fw + l * 129;
    float acc = f[0] + ((n & 1) ? -f[128] : f[128]);
    float nn = (float)n;
#pragma unroll 4
    for (int k = 1; k < 128; ++k)
        acc += 2.0f * f[k] * cospif((float)k * nn * (1.0f / 128.0f));
    g_dev[l * NMODES + n] = acc * (1.0f / 256.0f);
}

// chunk 0: encoder W1^T; chunks 1..16: circulant B_l^T (64-K slices), all
// pre-swizzled: element stored at (n, pos*8+jj) comes from source
// k = (pos ^ (n&7))*8 + jj within the chunk.
__global__ void build_wsw(const float* __restrict__ W1, const float* __restrict__ lw) {
    int id = blockIdx.x >> 8;
    int n  = blockIdx.x & 255;
    int j  = threadIdx.x;           // 0..63
    int pos = j >> 3, jj = j & 7;
    int k = ((pos ^ (n & 7)) << 3) + jj;
    float v;
    if (id == 0) {
        v = W1[k * NMODES + n];
    } else {
        int t = id - 1, l = t >> 2;
        int kg = (t & 3) * 64 + k;
        v = (kg <= 252) ? g_dev[l * NMODES + ((n - kg - 3) & 255)] : 0.0f;
        if (kg == n) v += lw[l * NMODES + kg];
    }
    w_sw[(((size_t)id << 8) + n) * 64 + j] = __float2half_rn(v);
}

// ---------------- weight-chunk prefetch (linear copy of packed image) -------
__device__ __forceinline__ void prefetch_chunk(int id, uint32_t wsmem, int tid) {
    const char* src = (const char*)(w_sw + ((size_t)id << 14));
#pragma unroll
    for (int i = 0; i < 8; ++i) {
        int idx = tid + i * NTHREADS;
        CP_ASYNC16(wsmem + idx * 16, src + idx * 16);
    }
    CP_COMMIT();
}

// ---------------- main ----------------
__global__ __launch_bounds__(NTHREADS, 2)
void fno_main(const float* __restrict__ mu, const float* __restrict__ xin,
              const float* __restrict__ b1, const float* __restrict__ W2,
              const float* __restrict__ b2v, float* __restrict__ out) {
    extern __shared__ __align__(16) char smem[];
    const uint32_t sb = smem_u32(smem);
    uint32_t* hw = (uint32_t*)smem;
    float* g_all = (float*)(smem + G_OFF);
    float* x_s   = (float*)(smem + X_OFF);
    float* w2_s  = (float*)(smem + W2_OFF);

    const int tid  = threadIdx.x;
    const int lane = tid & 31;
    const int warp = tid >> 5;
    const int lg   = lane >> 2;
    const int tig  = lane & 3;
    const int wm   = warp >> 2;   // 0..1
    const int wn   = warp & 3;    // 0..3
    const size_t row0 = (size_t)blockIdx.x * MROWS;

    prefetch_chunk(0, sb + WBUF0_OFF, tid);

    for (int i = tid; i < 5 * NMODES; i += NTHREADS)
        g_all[i] = (i < NMODES) ? b1[i] : g_dev[i - NMODES];
    for (int i = tid; i < MROWS * 3; i += NTHREADS) {
        int r = i / 3, c = i - r * 3;
        x_s[r * 4 + c] = xin[(row0 + r) * 3 + c];
    }
    if (tid < NMODES) w2_s[tid] = W2[tid];

    // mu -> h fp16 words [r][0..31]
    for (int i = tid; i < MROWS * 32; i += NTHREADS) {
        int r = i >> 5, w = i & 31;
        float2 v = ((const float2*)(mu + (row0 + r) * 64))[w];
        __half2 h2 = __floats2half2_rn(v.x, v.y);
        hw[r * HW + w] = *(const uint32_t*)&h2;
    }

    // ldmatrix lane bases
    // A: tiles (m0-7,k0-7h)(m8-15,k0-7h)(m0-7,k8-15h)(m8-15,k8-15h)
    const int a_row = lane & 15;
    const uint32_t a_koff = (uint32_t)((lane >> 4) << 4);
    uint32_t a_base[2];
#pragma unroll
    for (int mt = 0; mt < 2; ++mt)
        a_base[mt] = sb + (wm * 32 + mt * 16 + a_row) * (HW * 4) + a_koff;
    // B (swizzled rows): n-row per lane; seg = ks*2 + hi, xor row-low bits
    const int b_nloc = ((lane & 16) >> 1) + (lane & 7);
    const int hi = (lane >> 3) & 1;
    uint32_t b_base[4];
    int bx[4];
#pragma unroll
    for (int ntp = 0; ntp < 4; ++ntp) {
        int n = wn * 64 + ntp * 16 + b_nloc;
        b_base[ntp] = (uint32_t)(n << 7);
        bx[ntp] = n & 7;
    }

    float acc[2][8][4];
    int id = 0;
    for (int stage = 0; stage < 5; ++stage) {
        const int nch = (stage == 0) ? 1 : 4;
#pragma unroll
        for (int mt = 0; mt < 2; ++mt)
#pragma unroll
            for (int nt = 0; nt < 8; ++nt)
#pragma unroll
                for (int j = 0; j < 4; ++j) acc[mt][nt][j] = 0.0f;

#pragma unroll 1
        for (int c = 0; c < nch; ++c) {
            // chunk id's copy was issued >=1 gemm ago; wait, then one barrier
            // proves (a) chunk id visible from all threads, (b) all warps done
            // reading buffer (id+1)&1 (gemm id-1) -> safe to overwrite.
            CP_WAIT(0);
            __syncthreads();
            if (id + 1 < NCHUNKS)
                prefetch_chunk(id + 1, sb + ((id + 1) & 1 ? WBUF1_OFF : WBUF0_OFF), tid);

            const uint32_t wbase = sb + ((id & 1) ? WBUF1_OFF : WBUF0_OFF);
            const int kwbase = (stage == 0) ? 0 : c * 32;   // words

            uint32_t a[2][4], bb[2][4];
            ldsm_x4(a[0][0], a[0][1], a[0][2], a[0][3], a_base[0] + kwbase * 4);
            ldsm_x4(a[1][0], a[1][1], a[1][2], a[1][3], a_base[1] + kwbase * 4);
            ldsm_x4(bb[0][0], bb[0][1], bb[0][2], bb[0][3],
                    wbase + b_base[0] + (uint32_t)(((hi ^ bx[0]) & 7) << 4));
#pragma unroll
            for (int i = 0; i < 16; ++i) {
                const int ks = i >> 2, ntp = i & 3;
                uint32_t* bc = bb[i & 1];
                uint32_t* bn = bb[(i + 1) & 1];
                if (i < 15) {
                    const int i2 = i + 1, ks2 = i2 >> 2, ntp2 = i2 & 3;
                    const int seg2 = ks2 * 2 + hi;
                    ldsm_x4(bn[0], bn[1], bn[2], bn[3],
                            wbase + b_base[ntp2] + (uint32_t)(((seg2 ^ bx[ntp2]) & 7) << 4));
                }
                mma16(acc[0][2 * ntp],     a[0], bc[0], bc[1]);
                mma16(acc[1][2 * ntp],     a[1], bc[0], bc[1]);
                mma16(acc[0][2 * ntp + 1], a[0], bc[2], bc[3]);
                mma16(acc[1][2 * ntp + 1], a[1], bc[2], bc[3]);
                if (ntp == 3 && ks < 3) {
                    const int kw = kwbase + (ks + 1) * 8;
                    ldsm_x4(a[0][0], a[0][1], a[0][2], a[0][3], a_base[0] + kw * 4);
                    ldsm_x4(a[1][0], a[1][1], a[1][2], a[1][3], a_base[1] + kw * 4);
                }
            }
            ++id;
        }
        __syncthreads();   // all warps done reading h this stage

        // epilogue
        const float* gs = g_all + stage * NMODES;
        const bool last = (stage == 4);
#pragma unroll
        for (int mt = 0; mt < 2; ++mt)
#pragma unroll
            for (int half = 0; half < 2; ++half) {
                int r = wm * 32 + mt * 16 + half * 8 + lg;
                float x0 = x_s[r * 4 + 0];
                float x1 = x_s[r * 4 + 1];
                float x2 = x_s[r * 4 + 2];
#pragma unroll
                for (int nt = 0; nt < 8; ++nt) {
                    int n = wn * 64 + nt * 8 + 2 * tig;
                    float v0 = acc[mt][nt][half * 2 + 0];
                    float v1 = acc[mt][nt][half * 2 + 1];
                    if (stage == 0) {
                        v0 += gs[n]; v1 += gs[n + 1];
                    } else {
                        v0 += x0 * gs[n] + x1 * gs[(n + 255) & 255] + x2 * gs[(n + 254) & 255];
                        int n1 = n + 1;
                        v1 += x0 * gs[n1] + x1 * gs[(n1 + 255) & 255] + x2 * gs[(n1 + 254) & 255];
                    }
                    v0 = fmaxf(v0, 0.0f);
                    v1 = fmaxf(v1, 0.0f);
                    if (!last) {
                        __half2 h2 = __floats2half2_rn(v0, v1);
                        hw[r * HW + wn * 32 + nt * 4 + tig] = *(const uint32_t*)&h2;
                    } else {
                        *(float2*)((float*)smem + r * FH_STRIDE + n) = make_float2(v0, v1);
                    }
                }
            }
    }
    __syncthreads();

    // decoder: out[r] = h[r,:] . W2 + b2   (4 lanes per row)
    {
        const int r = tid >> 2, p = tid & 3;
        const float* hp = (const float*)smem + r * FH_STRIDE + p * 64;
        const float* wp = w2_s + p * 64;
        float s = 0.0f;
#pragma unroll
        for (int i = 0; i < 64; i += 2) {
            int j = (i + 8 * p) & 63;
            float2 hv = *(const float2*)(hp + j);
            s += hv.x * wp[j] + hv.y * wp[j + 1];
        }
        s += __shfl_xor_sync(0xffffffffu, s, 1);
        s += __shfl_xor_sync(0xffffffffu, s, 2);
        if (p == 0) out[row0 + r] = s + b2v[0];
    }
}

// ---------------------------------------------------------------------------
extern "C" void kernel_launch(void* const* d_in, const int* in_sizes, int n_in,
                              void* d_out, int out_size) {
    const float* mu = (const float*)d_in[0];
    const float* x  = (const float*)d_in[1];
    const float* W1 = (const float*)d_in[2];
    const float* b1 = (const float*)d_in[3];
    const float* fw = (const float*)d_in[4];
    const float* lw = (const float*)d_in[5];
    const float* W2 = (const float*)d_in[6];
    const float* b2 = (const float*)d_in[7];
    float* out = (float*)d_out;

    const int B = in_sizes[0] / 64;
    const int nblocks = B / MROWS;

    build_g<<<NLAYERS, NMODES>>>(fw);
    build_wsw<<<NCHUNKS * NMODES, 64>>>(W1, lw);

    cudaFuncSetAttribute(fno_main, cudaFuncAttributeMaxDynamicSharedMemorySize, SMEM_TOTAL);
    fno_main<<<nblocks, NTHREADS, SMEM_TOTAL>>>(mu, x, b1, W2, b2, out);
}

// round 7
// speedup vs baseline: 1.0040x; 1.0040x over previous
#include <cuda_runtime.h>
#include <cuda_fp16.h>
#include <cstdint>

// ---------------------------------------------------------------------------
// FNO on sm_103a, fp16 HMMA (m16n8k16) + swizzled-weight cp.async pipeline.
//   h0 = relu(mu @ W1 + b1)
//   h  = relu(h @ B_l + x-term_l)   l=0..3  (circulant form of rfft*fw->irfft)
//   out = h @ W2 + b2
// Weights pre-packed in global EXACTLY as the smem image (XOR-swizzled 128B
// rows, 32KB per 64-K chunk) -> linear cp.async, conflict-free ldmatrix.
// 256 threads, 64 rows/CTA, 104KB SMEM -> 2 CTAs/SM.
// Deep fragment pipeline: B ldsm 2 iterations ahead (3 buffers), A ldsm one
// ks-group ahead (double buffer) -> hides LDSM latency under MMA issue.
// ---------------------------------------------------------------------------

#define NMODES 256
#define NLAYERS 4
#define MROWS 64
#define NTHREADS 256
#define HW 132                        // h row stride in 32-bit words
#define H_BYTES (MROWS * HW * 4)      // 33792
#define WBUF_BYTES (NMODES * 128)     // 32768 (swizzled, no pad)
#define WBUF0_OFF H_BYTES
#define WBUF1_OFF (WBUF0_OFF + WBUF_BYTES)
#define G_OFF  (WBUF1_OFF + WBUF_BYTES)      // 99328
#define X_OFF  (G_OFF + 5 * NMODES * 4)      // 104448
#define W2_OFF (X_OFF + MROWS * 4 * 4)       // 105472
#define SMEM_TOTAL (W2_OFF + NMODES * 4)     // 106496 = 104KB
#define FH_STRIDE 260                 // final fp32 h row stride (floats)
#define NCHUNKS (1 + NLAYERS * 4)     // 17

__device__ float g_dev[NLAYERS * NMODES];
// packed weight image: [chunk][n][64 halves], row pre-swizzled so that the
// 16B segment at position p holds source k-segment (p ^ (n&7)).
__device__ __align__(16) __half w_sw[NCHUNKS * NMODES * 64];

__device__ __forceinline__ uint32_t smem_u32(const void* p) {
    uint32_t a;
    asm("{ .reg .u64 t; cvta.to.shared.u64 t, %1; cvt.u32.u64 %0, t; }" : "=r"(a) : "l"(p));
    return a;
}

#define CP_ASYNC16(dst, src) \
    asm volatile("cp.async.cg.shared.global [%0], [%1], 16;" :: "r"(dst), "l"(src) : "memory")
#define CP_COMMIT() asm volatile("cp.async.commit_group;" ::: "memory")
#define CP_WAIT(n)  asm volatile("cp.async.wait_group %0;" :: "n"(n) : "memory")

__device__ __forceinline__ void mma16(float* c, const uint32_t* a, uint32_t b0, uint32_t b1) {
    asm volatile(
        "mma.sync.aligned.m16n8k16.row.col.f32.f16.f16.f32 "
        "{%0,%1,%2,%3}, {%4,%5,%6,%7}, {%8,%9}, {%0,%1,%2,%3};\n"
        : "+f"(c[0]), "+f"(c[1]), "+f"(c[2]), "+f"(c[3])
        : "r"(a[0]), "r"(a[1]), "r"(a[2]), "r"(a[3]), "r"(b0), "r"(b1));
}

__device__ __forceinline__ void ldsm_x4(uint32_t& r0, uint32_t& r1, uint32_t& r2, uint32_t& r3,
                                        uint32_t addr) {
    asm volatile("ldmatrix.sync.aligned.m8n8.x4.shared.b16 {%0,%1,%2,%3}, [%4];"
                 : "=r"(r0), "=r"(r1), "=r"(r2), "=r"(r3) : "r"(addr));
}

// ---------------- preludes ----------------
__global__ void build_g(const float* __restrict__ fw) {
    int l = blockIdx.x, n = threadIdx.x;
    const float* f = fw + l * 129;
    float acc = f[0] + ((n & 1) ? -f[128] : f[128]);
    float nn = (float)n;
#pragma unroll 4
    for (int k = 1; k < 128; ++k)
        acc += 2.0f * f[k] * cospif((float)k * nn * (1.0f / 128.0f));
    g_dev[l * NMODES + n] = acc * (1.0f / 256.0f);
}

// chunk 0: encoder W1^T; chunks 1..16: circulant B_l^T (64-K slices), all
// pre-swizzled: element at (n, pos*8+jj) comes from k = (pos ^ (n&7))*8 + jj.
__global__ void build_wsw(const float* __restrict__ W1, const float* __restrict__ lw) {
    int id = blockIdx.x >> 8;
    int n  = blockIdx.x & 255;
    int j  = threadIdx.x;           // 0..63
    int pos = j >> 3, jj = j & 7;
    int k = ((pos ^ (n & 7)) << 3) + jj;
    float v;
    if (id == 0) {
        v = W1[k * NMODES + n];
    } else {
        int t = id - 1, l = t >> 2;
        int kg = (t & 3) * 64 + k;
        v = (kg <= 252) ? g_dev[l * NMODES + ((n - kg - 3) & 255)] : 0.0f;
        if (kg == n) v += lw[l * NMODES + kg];
    }
    w_sw[(((size_t)id << 8) + n) * 64 + j] = __float2half_rn(v);
}

// ---------------- weight-chunk prefetch (linear copy of packed image) -------
__device__ __forceinline__ void prefetch_chunk(int id, uint32_t wsmem, int tid) {
    const char* src = (const char*)(w_sw + ((size_t)id << 14));
#pragma unroll
    for (int i = 0; i < 8; ++i) {
        int idx = tid + i * NTHREADS;
        CP_ASYNC16(wsmem + idx * 16, src + idx * 16);
    }
    CP_COMMIT();
}

// ---------------- main ----------------
__global__ __launch_bounds__(NTHREADS, 2)
void fno_main(const float* __restrict__ mu, const float* __restrict__ xin,
              const float* __restrict__ b1, const float* __restrict__ W2,
              const float* __restrict__ b2v, float* __restrict__ out) {
    extern __shared__ __align__(16) char smem[];
    const uint32_t sb = smem_u32(smem);
    uint32_t* hw = (uint32_t*)smem;
    float* g_all = (float*)(smem + G_OFF);
    float* x_s   = (float*)(smem + X_OFF);
    float* w2_s  = (float*)(smem + W2_OFF);

    const int tid  = threadIdx.x;
    const int lane = tid & 31;
    const int warp = tid >> 5;
    const int lg   = lane >> 2;
    const int tig  = lane & 3;
    const int wm   = warp >> 2;   // 0..1
    const int wn   = warp & 3;    // 0..3
    const size_t row0 = (size_t)blockIdx.x * MROWS;

    prefetch_chunk(0, sb + WBUF0_OFF, tid);

    for (int i = tid; i < 5 * NMODES; i += NTHREADS)
        g_all[i] = (i < NMODES) ? b1[i] : g_dev[i - NMODES];
    for (int i = tid; i < MROWS * 3; i += NTHREADS) {
        int r = i / 3, c = i - r * 3;
        x_s[r * 4 + c] = xin[(row0 + r) * 3 + c];
    }
    if (tid < NMODES) w2_s[tid] = W2[tid];

    // mu -> h fp16 words [r][0..31]
    for (int i = tid; i < MROWS * 32; i += NTHREADS) {
        int r = i >> 5, w = i & 31;
        float2 v = ((const float2*)(mu + (row0 + r) * 64))[w];
        __half2 h2 = __floats2half2_rn(v.x, v.y);
        hw[r * HW + w] = *(const uint32_t*)&h2;
    }

    // ldmatrix lane bases
    const int a_row = lane & 15;
    const uint32_t a_koff = (uint32_t)((lane >> 4) << 4);
    uint32_t a_base[2];
#pragma unroll
    for (int mt = 0; mt < 2; ++mt)
        a_base[mt] = sb + (wm * 32 + mt * 16 + a_row) * (HW * 4) + a_koff;
    // B (swizzled rows): n-row per lane; seg = ks*2 + hi, xor with n&7
    const int b_nloc = ((lane & 16) >> 1) + (lane & 7);
    const int hi = (lane >> 3) & 1;
    uint32_t b_base[4];
    int bx[4];
#pragma unroll
    for (int ntp = 0; ntp < 4; ++ntp) {
        int n = wn * 64 + ntp * 16 + b_nloc;
        b_base[ntp] = (uint32_t)(n << 7);
        bx[ntp] = n & 7;
    }

    float acc[2][8][4];
    int id = 0;
    for (int stage = 0; stage < 5; ++stage) {
        const int nch = (stage == 0) ? 1 : 4;
#pragma unroll
        for (int mt = 0; mt < 2; ++mt)
#pragma unroll
            for (int nt = 0; nt < 8; ++nt)
#pragma unroll
                for (int j = 0; j < 4; ++j) acc[mt][nt][j] = 0.0f;

#pragma unroll 1
        for (int c = 0; c < nch; ++c) {
            __syncthreads();   // other buffer free; h writes visible
            if (id + 1 < NCHUNKS) {
                prefetch_chunk(id + 1, sb + ((id + 1) & 1 ? WBUF1_OFF : WBUF0_OFF), tid);
                CP_WAIT(1);    // chunk id landed; id+1 stays in flight
            } else {
                CP_WAIT(0);
            }
            __syncthreads();
            const uint32_t wbase = sb + ((id & 1) ? WBUF1_OFF : WBUF0_OFF);
            const int kwbase = (stage == 0) ? 0 : c * 32;   // words

            uint32_t a[2][2][4];   // [ks&1][mt][frag]
            uint32_t bb[3][4];     // 3-deep B pipeline

            ldsm_x4(a[0][0][0], a[0][0][1], a[0][0][2], a[0][0][3], a_base[0] + kwbase * 4);
            ldsm_x4(a[0][1][0], a[0][1][1], a[0][1][2], a[0][1][3], a_base[1] + kwbase * 4);
            ldsm_x4(bb[0][0], bb[0][1], bb[0][2], bb[0][3],
                    wbase + b_base[0] + (uint32_t)(((hi ^ bx[0]) & 7) << 4));
            ldsm_x4(bb[1][0], bb[1][1], bb[1][2], bb[1][3],
                    wbase + b_base[1] + (uint32_t)(((hi ^ bx[1]) & 7) << 4));
#pragma unroll
            for (int i = 0; i < 16; ++i) {
                const int ks = i >> 2, ntp = i & 3, kb = ks & 1;
                if (i + 2 < 16) {
                    const int i2 = i + 2, ks2 = i2 >> 2, ntp2 = i2 & 3;
                    const int seg2 = ks2 * 2 + hi;
                    uint32_t* bn = bb[i2 % 3];
                    ldsm_x4(bn[0], bn[1], bn[2], bn[3],
                            wbase + b_base[ntp2] + (uint32_t)(((seg2 ^ bx[ntp2]) & 7) << 4));
                }
                if (ntp == 1 && ks < 3) {
                    const int kw = kwbase + (ks + 1) * 8;
                    uint32_t* an0 = a[kb ^ 1][0];
                    uint32_t* an1 = a[kb ^ 1][1];
                    ldsm_x4(an0[0], an0[1], an0[2], an0[3], a_base[0] + kw * 4);
                    ldsm_x4(an1[0], an1[1], an1[2], an1[3], a_base[1] + kw * 4);
                }
                uint32_t* bc = bb[i % 3];
                mma16(acc[0][2 * ntp],     a[kb][0], bc[0], bc[1]);
                mma16(acc[1][2 * ntp],     a[kb][1], bc[0], bc[1]);
                mma16(acc[0][2 * ntp + 1], a[kb][0], bc[2], bc[3]);
                mma16(acc[1][2 * ntp + 1], a[kb][1], bc[2], bc[3]);
            }
            ++id;
        }
        __syncthreads();   // all warps done reading h this stage

        // epilogue
        const float* gs = g_all + stage * NMODES;
        const bool last = (stage == 4);
#pragma unroll
        for (int mt = 0; mt < 2; ++mt)
#pragma unroll
            for (int half = 0; half < 2; ++half) {
                int r = wm * 32 + mt * 16 + half * 8 + lg;
                float x0 = x_s[r * 4 + 0];
                float x1 = x_s[r * 4 + 1];
                float x2 = x_s[r * 4 + 2];
#pragma unroll
                for (int nt = 0; nt < 8; ++nt) {
                    int n = wn * 64 + nt * 8 + 2 * tig;
                    float v0 = acc[mt][nt][half * 2 + 0];
                    float v1 = acc[mt][nt][half * 2 + 1];
                    if (stage == 0) {
                        v0 += gs[n]; v1 += gs[n + 1];
                    } else {
                        v0 += x0 * gs[n] + x1 * gs[(n + 255) & 255] + x2 * gs[(n + 254) & 255];
                        int n1 = n + 1;
                        v1 += x0 * gs[n1] + x1 * gs[(n1 + 255) & 255] + x2 * gs[(n1 + 254) & 255];
                    }
                    v0 = fmaxf(v0, 0.0f);
                    v1 = fmaxf(v1, 0.0f);
                    if (!last) {
                        __half2 h2 = __floats2half2_rn(v0, v1);
                        hw[r * HW + wn * 32 + nt * 4 + tig] = *(const uint32_t*)&h2;
                    } else {
                        *(float2*)((float*)smem + r * FH_STRIDE + n) = make_float2(v0, v1);
                    }
                }
            }
    }
    __syncthreads();

    // decoder: out[r] = h[r,:] . W2 + b2   (4 lanes per row)
    {
        const int r = tid >> 2, p = tid & 3;
        const float* hp = (const float*)smem + r * FH_STRIDE + p * 64;
        const float* wp = w2_s + p * 64;
        float s = 0.0f;
#pragma unroll
        for (int i = 0; i < 64; i += 2) {
            int j = (i + 8 * p) & 63;
            float2 hv = *(const float2*)(hp + j);
            s += hv.x * wp[j] + hv.y * wp[j + 1];
        }
        s += __shfl_xor_sync(0xffffffffu, s, 1);
        s += __shfl_xor_sync(0xffffffffu, s, 2);
        if (p == 0) out[row0 + r] = s + b2v[0];
    }
}

// ---------------------------------------------------------------------------
extern "C" void kernel_launch(void* const* d_in, const int* in_sizes, int n_in,
                              void* d_out, int out_size) {
    const float* mu = (const float*)d_in[0];
    const float* x  = (const float*)d_in[1];
    const float* W1 = (const float*)d_in[2];
    const float* b1 = (const float*)d_in[3];
    const float* fw = (const float*)d_in[4];
    const float* lw = (const float*)d_in[5];
    const float* W2 = (const float*)d_in[6];
    const float* b2 = (const float*)d_in[7];
    float* out = (float*)d_out;

    const int B = in_sizes[0] / 64;
    const int nblocks = B / MROWS;

    build_g<<<NLAYERS, NMODES>>>(fw);
    build_wsw<<<NCHUNKS * NMODES, 64>>>(W1, lw);

    cudaFuncSetAttribute(fno_main, cudaFuncAttributeMaxDynamicSharedMemorySize, SMEM_TOTAL);
    fno_main<<<nblocks, NTHREADS, SMEM_TOTAL>>>(mu, x, b1, W2, b2, out);
}

// round 9
// speedup vs baseline: 1.1191x; 1.1147x over previous
#include <cuda_runtime.h>
#include <cuda_fp16.h>
#include <cstdint>

// ---------------------------------------------------------------------------
// FNO on sm_103a. Circulant Fourier layers computed WITHOUT materialized
// weights: B[k][n] = g[(n-k-3) mod 256], so each mma B-fragment register is
// one LDS.32 from a 2KB reversed-g pair table (per layer). Diagonal lw branch
// and the k>=253 crop are applied in the epilogue / via a lane mask.
//   h0 = relu(mu @ W1 + b1)           (W1 via one-shot cp.async, ldsm path)
//   h  = relu(conv_g(h) + x-term + h*lw)   l=0..3
//   out = h @ W2 + b2                 (fused into stage-4 epilogue, fp32)
// 256 threads, 64 rows/CTA, 85KB SMEM -> 2 CTAs/SM. No weight streaming.
// R9: fixed nt=1 b1 table immediate (192 -> 224).
// ---------------------------------------------------------------------------

#define NMODES 256
#define NLAYERS 4
#define MROWS 64
#define NTHREADS 256
#define HW 132                              // h row stride in 32-bit words
#define H_BYTES (MROWS * HW * 4)            // 33792
#define W1_OFF  H_BYTES                     // 32KB swizzled W1 image
#define T2_OFF  (W1_OFF + 32768)            // 66560: 4 x 2048B pair tables
#define GALL_OFF (T2_OFF + NLAYERS * 2048)  // 74752: b1 + 4x g (fp32)
#define LW_OFF  (GALL_OFF + 5 * NMODES * 4) // 79872: 4x lw (fp32)
#define XS_OFF  (LW_OFF + NLAYERS * NMODES * 4) // 83968
#define W2S_OFF (XS_OFF + MROWS * 4 * 4)    // 84992
#define DEC_OFF (W2S_OFF + NMODES * 4)      // 86016: 64x4 decoder partials
#define SMEM_TOTAL (DEC_OFF + MROWS * 4 * 4) // 87040

__device__ float g_dev[NLAYERS * NMODES];
__device__ __align__(16) uint32_t t2_dev[NLAYERS * 512]; // half2 pair tables
__device__ __align__(16) __half w1sw_dev[NMODES * 64];   // swizzled W1^T image

__device__ __forceinline__ uint32_t smem_u32(const void* p) {
    uint32_t a;
    asm("{ .reg .u64 t; cvta.to.shared.u64 t, %1; cvt.u32.u64 %0, t; }" : "=r"(a) : "l"(p));
    return a;
}

#define CP_ASYNC16(dst, src) \
    asm volatile("cp.async.cg.shared.global [%0], [%1], 16;" :: "r"(dst), "l"(src) : "memory")
#define CP_COMMIT() asm volatile("cp.async.commit_group;" ::: "memory")
#define CP_WAIT0()  asm volatile("cp.async.wait_group 0;" ::: "memory")

#define LDS_B(dst, base, imm) \
    asm volatile("ld.shared.b32 %0, [%1+%2];" : "=r"(dst) : "r"(base), "n"(imm))

__device__ __forceinline__ void mma16(float* c, const uint32_t* a, uint32_t b0, uint32_t b1) {
    asm volatile(
        "mma.sync.aligned.m16n8k16.row.col.f32.f16.f16.f32 "
        "{%0,%1,%2,%3}, {%4,%5,%6,%7}, {%8,%9}, {%0,%1,%2,%3};\n"
        : "+f"(c[0]), "+f"(c[1]), "+f"(c[2]), "+f"(c[3])
        : "r"(a[0]), "r"(a[1]), "r"(a[2]), "r"(a[3]), "r"(b0), "r"(b1));
}

__device__ __forceinline__ void ldsm_x4(uint32_t& r0, uint32_t& r1, uint32_t& r2, uint32_t& r3,
                                        uint32_t addr) {
    asm volatile("ldmatrix.sync.aligned.m8n8.x4.shared.b16 {%0,%1,%2,%3}, [%4];"
                 : "=r"(r0), "=r"(r1), "=r"(r2), "=r"(r3) : "r"(addr));
}

// ---------------- preludes ----------------
__global__ void build_g(const float* __restrict__ fw) {
    int l = blockIdx.x, n = threadIdx.x;
    const float* f = fw + l * 129;
    float acc = f[0] + ((n & 1) ? -f[128] : f[128]);
    float nn = (float)n;
#pragma unroll 4
    for (int k = 1; k < 128; ++k)
        acc += 2.0f * f[k] * cospif((float)k * nn * (1.0f / 128.0f));
    g_dev[l * NMODES + n] = acc * (1.0f / 256.0f);
}

// pair table: t2[l][i] = half2{ g_l[(252-i)&255], g_l[(251-i)&255] }, i<511
__global__ void build_t2() {
    int l = blockIdx.x, i = threadIdx.x + 256 * blockIdx.y;
    if (i >= 512) return;
    uint32_t v = 0;
    if (i < 511) {
        __half lo = __float2half_rn(g_dev[l * NMODES + ((252 - i) & 255)]);
        __half hi = __float2half_rn(g_dev[l * NMODES + ((251 - i) & 255)]);
        __half2 h2 = __halves2half2(lo, hi);
        v = *(const uint32_t*)&h2;
    }
    t2_dev[l * 512 + i] = v;
}

// swizzled W1^T image: element (n, pos*8+jj) <- W1[k=(pos^(n&7))*8+jj][n]
__global__ void build_w1sw(const float* __restrict__ W1) {
    int n = blockIdx.x, j = threadIdx.x;
    int pos = j >> 3, jj = j & 7;
    int k = ((pos ^ (n & 7)) << 3) + jj;
    w1sw_dev[n * 64 + j] = __float2half_rn(W1[k * NMODES + n]);
}

// ---------------- main ----------------
__global__ __launch_bounds__(NTHREADS, 2)
void fno_main(const float* __restrict__ mu, const float* __restrict__ xin,
              const float* __restrict__ b1, const float* __restrict__ lw,
              const float* __restrict__ W2, const float* __restrict__ b2v,
              float* __restrict__ out) {
    extern __shared__ __align__(16) char smem[];
    const uint32_t sb = smem_u32(smem);
    uint32_t* hw   = (uint32_t*)smem;
    uint32_t* t2s  = (uint32_t*)(smem + T2_OFF);
    float* g_all   = (float*)(smem + GALL_OFF);
    float* lw_s    = (float*)(smem + LW_OFF);
    float* x_s     = (float*)(smem + XS_OFF);
    float* w2_s    = (float*)(smem + W2S_OFF);
    float* dec     = (float*)(smem + DEC_OFF);

    const int tid  = threadIdx.x;
    const int lane = tid & 31;
    const int warp = tid >> 5;
    const int lg   = lane >> 2;   // 0..7
    const int tig  = lane & 3;    // 0..3
    const int wm   = warp >> 2;   // 0..1
    const int wn   = warp & 3;    // 0..3
    const size_t row0 = (size_t)blockIdx.x * MROWS;

    // one-shot W1 image copy
    {
        const char* src = (const char*)w1sw_dev;
#pragma unroll
        for (int i = 0; i < 8; ++i) {
            int idx = tid + i * NTHREADS;
            CP_ASYNC16(sb + W1_OFF + idx * 16, src + idx * 16);
        }
        CP_COMMIT();
    }

    // tables & small data
    for (int i = tid; i < NLAYERS * 512; i += NTHREADS) t2s[i] = t2_dev[i];
    for (int i = tid; i < 5 * NMODES; i += NTHREADS)
        g_all[i] = (i < NMODES) ? b1[i] : g_dev[i - NMODES];
    for (int i = tid; i < NLAYERS * NMODES; i += NTHREADS) lw_s[i] = lw[i];
    for (int i = tid; i < MROWS * 3; i += NTHREADS) {
        int r = i / 3, c = i - r * 3;
        x_s[r * 4 + c] = xin[(row0 + r) * 3 + c];
    }
    if (tid < NMODES) w2_s[tid] = W2[tid];

    // mu -> h fp16 words [r][0..31]
    for (int i = tid; i < MROWS * 32; i += NTHREADS) {
        int r = i >> 5, w = i & 31;
        float2 v = ((const float2*)(mu + (row0 + r) * 64))[w];
        __half2 h2 = __floats2half2_rn(v.x, v.y);
        hw[r * HW + w] = *(const uint32_t*)&h2;
    }

    // A ldsm lane bases
    const int a_row = lane & 15;
    const uint32_t a_koff = (uint32_t)((lane >> 4) << 4);
    uint32_t a_base[2];
#pragma unroll
    for (int mt = 0; mt < 2; ++mt)
        a_base[mt] = sb + (wm * 32 + mt * 16 + a_row) * (HW * 4) + a_koff;

    // W1 (swizzled) ldsm lane bases
    const int b_nloc = ((lane & 16) >> 1) + (lane & 7);
    const int hi = (lane >> 3) & 1;
    uint32_t w1_off[4];
    int bx[4];
#pragma unroll
    for (int ntp = 0; ntp < 4; ++ntp) {
        int n = wn * 64 + ntp * 16 + b_nloc;
        w1_off[ntp] = (uint32_t)(n << 7);
        bx[ntp] = n & 7;
    }

    // circulant-table per-lane base (biased by -224 so nt immediates >= 0)
    // addr(l, ks, nt, b) = rb_l + 64*ks + (224 - 32*nt) + 32*b
    const uint32_t rb0 = sb + T2_OFF + 1020u + 8u * tig - 4u * lg - 256u * wn - 224u;
    // crop mask for k in {253,254,255} (slice ks=15, b1 regs)
    const uint32_t cmask = (tig <= 1) ? 0xFFFFFFFFu : (tig == 2 ? 0x0000FFFFu : 0u);

    float acc[2][8][4];
#define ZERO_ACC()                                   \
    _Pragma("unroll") for (int mt = 0; mt < 2; ++mt) \
    _Pragma("unroll") for (int nt = 0; nt < 8; ++nt) \
    _Pragma("unroll") for (int j = 0; j < 4; ++j) acc[mt][nt][j] = 0.0f;

    CP_WAIT0();
    __syncthreads();

    // ---------------- encoder gemm (K=64, W1 image via ldsm) ----------------
    ZERO_ACC();
    {
        const uint32_t wbase = sb + W1_OFF;
#pragma unroll
        for (int ks = 0; ks < 4; ++ks) {
            uint32_t a[2][4];
            ldsm_x4(a[0][0], a[0][1], a[0][2], a[0][3], a_base[0] + ks * 32);
            ldsm_x4(a[1][0], a[1][1], a[1][2], a[1][3], a_base[1] + ks * 32);
            const int seg = ks * 2 + hi;
#pragma unroll
            for (int ntp = 0; ntp < 4; ++ntp) {
                uint32_t b0, b1r, b2, b3;
                ldsm_x4(b0, b1r, b2, b3,
                        wbase + w1_off[ntp] + (uint32_t)(((seg ^ bx[ntp]) & 7) << 4));
                mma16(acc[0][2 * ntp],     a[0], b0, b1r);
                mma16(acc[1][2 * ntp],     a[1], b0, b1r);
                mma16(acc[0][2 * ntp + 1], a[0], b2, b3);
                mma16(acc[1][2 * ntp + 1], a[1], b2, b3);
            }
        }
    }
    __syncthreads();
    // encoder epilogue: relu(acc + b1) -> h
#pragma unroll
    for (int mt = 0; mt < 2; ++mt)
#pragma unroll
        for (int half = 0; half < 2; ++half) {
            int r = wm * 32 + mt * 16 + half * 8 + lg;
#pragma unroll
            for (int nt = 0; nt < 8; ++nt) {
                int n = wn * 64 + nt * 8 + 2 * tig;
                float v0 = fmaxf(acc[mt][nt][half * 2 + 0] + g_all[n], 0.0f);
                float v1 = fmaxf(acc[mt][nt][half * 2 + 1] + g_all[n + 1], 0.0f);
                __half2 h2 = __floats2half2_rn(v0, v1);
                hw[r * HW + wn * 32 + nt * 4 + tig] = *(const uint32_t*)&h2;
            }
        }
    __syncthreads();

    // ---------------- Fourier stages ----------------
    float dsum[4];
#pragma unroll
    for (int s = 0; s < 4; ++s) dsum[s] = 0.0f;

#pragma unroll 1
    for (int l = 1; l <= 4; ++l) {
        ZERO_ACC();
        uint32_t rb = rb0 + (uint32_t)((l - 1) * 2048);
        uint32_t ra0 = a_base[0], ra1 = a_base[1];

#define B_SLICE(CROP)                                                          \
        do {                                                                   \
            uint32_t a[2][4], b0[8], b1[8];                                    \
            ldsm_x4(a[0][0], a[0][1], a[0][2], a[0][3], ra0);                  \
            ldsm_x4(a[1][0], a[1][1], a[1][2], a[1][3], ra1);                  \
            LDS_B(b0[0], rb, 224); LDS_B(b1[0], rb, 256);                      \
            LDS_B(b0[1], rb, 192); LDS_B(b1[1], rb, 224);                      \
            LDS_B(b0[2], rb, 160); LDS_B(b1[2], rb, 192);                      \
            LDS_B(b0[3], rb, 128); LDS_B(b1[3], rb, 160);                      \
            LDS_B(b0[4], rb,  96); LDS_B(b1[4], rb, 128);                      \
            LDS_B(b0[5], rb,  64); LDS_B(b1[5], rb,  96);                      \
            LDS_B(b0[6], rb,  32); LDS_B(b1[6], rb,  64);                      \
            LDS_B(b0[7], rb,   0); LDS_B(b1[7], rb,  32);                      \
            if (CROP) {                                                        \
                _Pragma("unroll") for (int nt = 0; nt < 8; ++nt) b1[nt] &= cmask; \
            }                                                                  \
            _Pragma("unroll") for (int nt = 0; nt < 8; ++nt) {                 \
                mma16(acc[0][nt], a[0], b0[nt], b1[nt]);                       \
                mma16(acc[1][nt], a[1], b0[nt], b1[nt]);                       \
            }                                                                  \
            ra0 += 32; ra1 += 32; rb += 64;                                    \
        } while (0)

#pragma unroll 3
        for (int ks = 0; ks < 15; ++ks) B_SLICE(false);
        B_SLICE(true);   // ks = 15: crop k = 253,254,255
#undef B_SLICE

        __syncthreads();

        const float* gs  = g_all + l * NMODES;
        const float* lws = lw_s + (l - 1) * NMODES;
        const bool last = (l == 4);
#pragma unroll
        for (int mt = 0; mt < 2; ++mt)
#pragma unroll
            for (int half = 0; half < 2; ++half) {
                int r = wm * 32 + mt * 16 + half * 8 + lg;
                float x0 = x_s[r * 4 + 0];
                float x1 = x_s[r * 4 + 1];
                float x2 = x_s[r * 4 + 2];
#pragma unroll
                for (int nt = 0; nt < 8; ++nt) {
                    int n = wn * 64 + nt * 8 + 2 * tig;
                    const int widx = r * HW + wn * 32 + nt * 4 + tig;
                    uint32_t hraw = hw[widx];
                    __half2 ho = *(const __half2*)&hraw;
                    float2 lw2 = *(const float2*)(lws + n);
                    float v0 = acc[mt][nt][half * 2 + 0]
                             + x0 * gs[n] + x1 * gs[(n + 255) & 255] + x2 * gs[(n + 254) & 255]
                             + __low2float(ho) * lw2.x;
                    int n1 = n + 1;
                    float v1 = acc[mt][nt][half * 2 + 1]
                             + x0 * gs[n1] + x1 * gs[(n1 + 255) & 255] + x2 * gs[(n1 + 254) & 255]
                             + __high2float(ho) * lw2.y;
                    v0 = fmaxf(v0, 0.0f);
                    v1 = fmaxf(v1, 0.0f);
                    if (!last) {
                        __half2 h2 = __floats2half2_rn(v0, v1);
                        hw[widx] = *(const uint32_t*)&h2;
                    } else {
                        float2 w2v = *(const float2*)(w2_s + n);
                        dsum[mt * 2 + half] += v0 * w2v.x + v1 * w2v.y;
                    }
                }
            }
        if (!last) __syncthreads();
    }

    // ---------------- decoder reduction ----------------
#pragma unroll
    for (int s = 0; s < 4; ++s) {
        dsum[s] += __shfl_xor_sync(0xffffffffu, dsum[s], 1);
        dsum[s] += __shfl_xor_sync(0xffffffffu, dsum[s], 2);
    }
    if (tig == 0) {
#pragma unroll
        for (int s = 0; s < 4; ++s) {
            int mt = s >> 1, half = s & 1;
            int r = wm * 32 + mt * 16 + half * 8 + lg;
            dec[r * 4 + wn] = dsum[s];
        }
    }
    __syncthreads();
    if (tid < MROWS) {
        const float* d = dec + tid * 4;
        out[row0 + tid] = d[0] + d[1] + d[2] + d[3] + b2v[0];
    }
}

// ---------------------------------------------------------------------------
extern "C" void kernel_launch(void* const* d_in, const int* in_sizes, int n_in,
                              void* d_out, int out_size) {
    const float* mu = (const float*)d_in[0];
    const float* x  = (const float*)d_in[1];
    const float* W1 = (const float*)d_in[2];
    const float* b1 = (const float*)d_in[3];
    const float* fw = (const float*)d_in[4];
    const float* lw = (const float*)d_in[5];
    const float* W2 = (const float*)d_in[6];
    const float* b2 = (const float*)d_in[7];
    float* out = (float*)d_out;

    const int B = in_sizes[0] / 64;
    const int nblocks = B / MROWS;

    build_g<<<NLAYERS, NMODES>>>(fw);
    build_t2<<<dim3(NLAYERS, 2), 256>>>();
    build_w1sw<<<NMODES, 64>>>(W1);

    cudaFuncSetAttribute(fno_main, cudaFuncAttributeMaxDynamicSharedMemorySize, SMEM_TOTAL);
    fno_main<<<nblocks, NTHREADS, SMEM_TOTAL>>>(mu, x, b1, lw, W2, b2, out);
}

// round 10
// speedup vs baseline: 1.1536x; 1.0308x over previous
#include <cuda_runtime.h>
#include <cuda_fp16.h>
#include <cstdint>

// ---------------------------------------------------------------------------
// FNO on sm_103a. Circulant Fourier layers via a 2KB reversed-g pair table:
// B[k][n] = g[(n-k-3) mod 256]; mma B-fragments come from a 9-register
// sliding window over the table (2 new LDS.32 per K-slice). Diagonal lw and
// the k>=253 crop applied in epilogue / lane mask.
//   h0 = relu(mu @ W1 + b1)           (W1 via one-shot cp.async, ldsm path)
//   h  = relu(conv_g(h) + x-term + h*lw)   l=0..3
//   out = h @ W2 + b2                 (fused into stage-4 epilogue, fp32)
// 256 threads, 64 rows/CTA, ~85KB SMEM -> 2 CTAs/SM. No weight streaming.
// R10: B-window register sharing (16 LDS/slice -> 2), A double-buffer,
//      haloed g_ext table (epilogue 6 LDS.32 -> 2 LDS.64).
// ---------------------------------------------------------------------------

#define NMODES 256
#define NLAYERS 4
#define MROWS 64
#define NTHREADS 256
#define HW 132                              // h row stride in 32-bit words
#define H_BYTES (MROWS * HW * 4)            // 33792
#define W1_OFF  H_BYTES                     // 32KB swizzled W1 image
#define T2_OFF  (W1_OFF + 32768)            // 66560: 4 x 2048B pair tables
#define B1_OFF  (T2_OFF + NLAYERS * 2048)   // 74752: b1 (fp32)
#define GEXT_OFF (B1_OFF + NMODES * 4)      // 75776: 4 x 260 haloed g (fp32)
#define LW_OFF  (GEXT_OFF + NLAYERS * 260 * 4) // 79936
#define XS_OFF  (LW_OFF + NLAYERS * NMODES * 4) // 84032
#define W2S_OFF (XS_OFF + MROWS * 4 * 4)    // 85056
#define DEC_OFF (W2S_OFF + NMODES * 4)      // 86080
#define SMEM_TOTAL (DEC_OFF + MROWS * 4 * 4) // 87104

__device__ float g_dev[NLAYERS * NMODES];
__device__ __align__(16) uint32_t t2_dev[NLAYERS * 512]; // half2 pair tables
__device__ __align__(16) __half w1sw_dev[NMODES * 64];   // swizzled W1^T image

__device__ __forceinline__ uint32_t smem_u32(const void* p) {
    uint32_t a;
    asm("{ .reg .u64 t; cvta.to.shared.u64 t, %1; cvt.u32.u64 %0, t; }" : "=r"(a) : "l"(p));
    return a;
}

#define CP_ASYNC16(dst, src) \
    asm volatile("cp.async.cg.shared.global [%0], [%1], 16;" :: "r"(dst), "l"(src) : "memory")
#define CP_COMMIT() asm volatile("cp.async.commit_group;" ::: "memory")
#define CP_WAIT0()  asm volatile("cp.async.wait_group 0;" ::: "memory")

#define LDS_B(dst, base, imm) \
    asm volatile("ld.shared.b32 %0, [%1+%2];" : "=r"(dst) : "r"(base), "n"(imm))

__device__ __forceinline__ void mma16(float* c, const uint32_t* a, uint32_t b0, uint32_t b1) {
    asm volatile(
        "mma.sync.aligned.m16n8k16.row.col.f32.f16.f16.f32 "
        "{%0,%1,%2,%3}, {%4,%5,%6,%7}, {%8,%9}, {%0,%1,%2,%3};\n"
        : "+f"(c[0]), "+f"(c[1]), "+f"(c[2]), "+f"(c[3])
        : "r"(a[0]), "r"(a[1]), "r"(a[2]), "r"(a[3]), "r"(b0), "r"(b1));
}

__device__ __forceinline__ void ldsm_x4(uint32_t& r0, uint32_t& r1, uint32_t& r2, uint32_t& r3,
                                        uint32_t addr) {
    asm volatile("ldmatrix.sync.aligned.m8n8.x4.shared.b16 {%0,%1,%2,%3}, [%4];"
                 : "=r"(r0), "=r"(r1), "=r"(r2), "=r"(r3) : "r"(addr));
}

// ---------------- preludes ----------------
__global__ void build_g(const float* __restrict__ fw) {
    int l = blockIdx.x, n = threadIdx.x;
    const float* f = fw + l * 129;
    float acc = f[0] + ((n & 1) ? -f[128] : f[128]);
    float nn = (float)n;
#pragma unroll 4
    for (int k = 1; k < 128; ++k)
        acc += 2.0f * f[k] * cospif((float)k * nn * (1.0f / 128.0f));
    g_dev[l * NMODES + n] = acc * (1.0f / 256.0f);
}

// pair table: t2[l][i] = half2{ g_l[(252-i)&255], g_l[(251-i)&255] }, i<511
__global__ void build_t2() {
    int l = blockIdx.x, i = threadIdx.x + 256 * blockIdx.y;
    if (i >= 512) return;
    uint32_t v = 0;
    if (i < 511) {
        __half lo = __float2half_rn(g_dev[l * NMODES + ((252 - i) & 255)]);
        __half hi = __float2half_rn(g_dev[l * NMODES + ((251 - i) & 255)]);
        __half2 h2 = __halves2half2(lo, hi);
        v = *(const uint32_t*)&h2;
    }
    t2_dev[l * 512 + i] = v;
}

// swizzled W1^T image: element (n, pos*8+jj) <- W1[k=(pos^(n&7))*8+jj][n]
__global__ void build_w1sw(const float* __restrict__ W1) {
    int n = blockIdx.x, j = threadIdx.x;
    int pos = j >> 3, jj = j & 7;
    int k = ((pos ^ (n & 7)) << 3) + jj;
    w1sw_dev[n * 64 + j] = __float2half_rn(W1[k * NMODES + n]);
}

// ---------------- main ----------------
__global__ __launch_bounds__(NTHREADS, 2)
void fno_main(const float* __restrict__ mu, const float* __restrict__ xin,
              const float* __restrict__ b1, const float* __restrict__ lw,
              const float* __restrict__ W2, const float* __restrict__ b2v,
              float* __restrict__ out) {
    extern __shared__ __align__(16) char smem[];
    const uint32_t sb = smem_u32(smem);
    uint32_t* hw   = (uint32_t*)smem;
    uint32_t* t2s  = (uint32_t*)(smem + T2_OFF);
    float* b1_s    = (float*)(smem + B1_OFF);
    float* gext    = (float*)(smem + GEXT_OFF);
    float* lw_s    = (float*)(smem + LW_OFF);
    float* x_s     = (float*)(smem + XS_OFF);
    float* w2_s    = (float*)(smem + W2S_OFF);
    float* dec     = (float*)(smem + DEC_OFF);

    const int tid  = threadIdx.x;
    const int lane = tid & 31;
    const int warp = tid >> 5;
    const int lg   = lane >> 2;   // 0..7
    const int tig  = lane & 3;    // 0..3
    const int wm   = warp >> 2;   // 0..1
    const int wn   = warp & 3;    // 0..3
    const size_t row0 = (size_t)blockIdx.x * MROWS;

    // one-shot W1 image copy
    {
        const char* src = (const char*)w1sw_dev;
#pragma unroll
        for (int i = 0; i < 8; ++i) {
            int idx = tid + i * NTHREADS;
            CP_ASYNC16(sb + W1_OFF + idx * 16, src + idx * 16);
        }
        CP_COMMIT();
    }

    // tables & small data
    for (int i = tid; i < NLAYERS * 512; i += NTHREADS) t2s[i] = t2_dev[i];
    if (tid < NMODES) b1_s[tid] = b1[tid];
    for (int i = tid; i < NLAYERS * 260; i += NTHREADS) {
        int l = i / 260, j = i - l * 260;
        gext[i] = g_dev[l * NMODES + ((j + 254) & 255)];  // g_ext[j] = g[(j-2) mod 256]
    }
    for (int i = tid; i < NLAYERS * NMODES; i += NTHREADS) lw_s[i] = lw[i];
    for (int i = tid; i < MROWS * 3; i += NTHREADS) {
        int r = i / 3, c = i - r * 3;
        x_s[r * 4 + c] = xin[(row0 + r) * 3 + c];
    }
    if (tid < NMODES) w2_s[tid] = W2[tid];

    // mu -> h fp16 words [r][0..31]
    for (int i = tid; i < MROWS * 32; i += NTHREADS) {
        int r = i >> 5, w = i & 31;
        float2 v = ((const float2*)(mu + (row0 + r) * 64))[w];
        __half2 h2 = __floats2half2_rn(v.x, v.y);
        hw[r * HW + w] = *(const uint32_t*)&h2;
    }

    // A ldsm lane bases
    const int a_row = lane & 15;
    const uint32_t a_koff = (uint32_t)((lane >> 4) << 4);
    uint32_t a_base[2];
#pragma unroll
    for (int mt = 0; mt < 2; ++mt)
        a_base[mt] = sb + (wm * 32 + mt * 16 + a_row) * (HW * 4) + a_koff;

    // W1 (swizzled) ldsm lane bases
    const int b_nloc = ((lane & 16) >> 1) + (lane & 7);
    const int hi = (lane >> 3) & 1;
    uint32_t w1_off[4];
    int bx[4];
#pragma unroll
    for (int ntp = 0; ntp < 4; ++ntp) {
        int n = wn * 64 + ntp * 16 + b_nloc;
        w1_off[ntp] = (uint32_t)(n << 7);
        bx[ntp] = n & 7;
    }

    // circulant-table per-lane base: addr(ks,nt,b) = rb + 64*ks + (256 - 32*(nt+1-b))
    const uint32_t rb0 = sb + T2_OFF + 1020u + 8u * tig - 4u * lg - 256u * wn - 224u;
    // crop mask for k in {253,254,255} (slice ks=15, b1 regs only)
    const uint32_t cmask = (tig <= 1) ? 0xFFFFFFFFu : (tig == 2 ? 0x0000FFFFu : 0u);

    float acc[2][8][4];
#define ZERO_ACC()                                   \
    _Pragma("unroll") for (int mt = 0; mt < 2; ++mt) \
    _Pragma("unroll") for (int nt = 0; nt < 8; ++nt) \
    _Pragma("unroll") for (int j = 0; j < 4; ++j) acc[mt][nt][j] = 0.0f;

    CP_WAIT0();
    __syncthreads();

    // ---------------- encoder gemm (K=64, W1 image via ldsm) ----------------
    ZERO_ACC();
    {
        const uint32_t wbase = sb + W1_OFF;
#pragma unroll
        for (int ks = 0; ks < 4; ++ks) {
            uint32_t a[2][4];
            ldsm_x4(a[0][0], a[0][1], a[0][2], a[0][3], a_base[0] + ks * 32);
            ldsm_x4(a[1][0], a[1][1], a[1][2], a[1][3], a_base[1] + ks * 32);
            const int seg = ks * 2 + hi;
#pragma unroll
            for (int ntp = 0; ntp < 4; ++ntp) {
                uint32_t b0, b1r, b2, b3;
                ldsm_x4(b0, b1r, b2, b3,
                        wbase + w1_off[ntp] + (uint32_t)(((seg ^ bx[ntp]) & 7) << 4));
                mma16(acc[0][2 * ntp],     a[0], b0, b1r);
                mma16(acc[1][2 * ntp],     a[1], b0, b1r);
                mma16(acc[0][2 * ntp + 1], a[0], b2, b3);
                mma16(acc[1][2 * ntp + 1], a[1], b2, b3);
            }
        }
    }
    __syncthreads();
    // encoder epilogue: relu(acc + b1) -> h
#pragma unroll
    for (int mt = 0; mt < 2; ++mt)
#pragma unroll
        for (int half = 0; half < 2; ++half) {
            int r = wm * 32 + mt * 16 + half * 8 + lg;
#pragma unroll
            for (int nt = 0; nt < 8; ++nt) {
                int n = wn * 64 + nt * 8 + 2 * tig;
                float2 bv = *(const float2*)(b1_s + n);
                float v0 = fmaxf(acc[mt][nt][half * 2 + 0] + bv.x, 0.0f);
                float v1 = fmaxf(acc[mt][nt][half * 2 + 1] + bv.y, 0.0f);
                __half2 h2 = __floats2half2_rn(v0, v1);
                hw[r * HW + wn * 32 + nt * 4 + tig] = *(const uint32_t*)&h2;
            }
        }
    __syncthreads();

    // ---------------- Fourier stages ----------------
    float dsum[4];
#pragma unroll
    for (int s = 0; s < 4; ++s) dsum[s] = 0.0f;

#pragma unroll 1
    for (int l = 1; l <= 4; ++l) {
        ZERO_ACC();
        uint32_t rb = rb0 + (uint32_t)((l - 1) * 2048);
        uint32_t ra0 = a_base[0], ra1 = a_base[1];

        // sliding window: v[j] = table[rb + 256 - 32j]; b1[nt]=v[nt], b0[nt]=v[nt+1]
        uint32_t v[9];
        uint32_t a[2][2][4];
        ldsm_x4(a[0][0][0], a[0][0][1], a[0][0][2], a[0][0][3], ra0);
        ldsm_x4(a[0][1][0], a[0][1][1], a[0][1][2], a[0][1][3], ra1);
        LDS_B(v[0], rb, 256); LDS_B(v[1], rb, 224); LDS_B(v[2], rb, 192);
        LDS_B(v[3], rb, 160); LDS_B(v[4], rb, 128); LDS_B(v[5], rb,  96);
        LDS_B(v[6], rb,  64); LDS_B(v[7], rb,  32); LDS_B(v[8], rb,   0);

#pragma unroll
        for (int ks = 0; ks < 16; ++ks) {
            const int cur = ks & 1, nxt = cur ^ 1;
            uint32_t nv0 = 0, nv1 = 0;
            if (ks < 15) {
                ldsm_x4(a[nxt][0][0], a[nxt][0][1], a[nxt][0][2], a[nxt][0][3], ra0 + 32);
                ldsm_x4(a[nxt][1][0], a[nxt][1][1], a[nxt][1][2], a[nxt][1][3], ra1 + 32);
                LDS_B(nv0, rb, 320);   // next slice v[0]
                LDS_B(nv1, rb, 288);   // next slice v[1]
            }
            uint32_t mb[8];
            if (ks == 15) {
#pragma unroll
                for (int nt = 0; nt < 8; ++nt) mb[nt] = v[nt] & cmask;
            }
#pragma unroll
            for (int nt = 0; nt < 8; ++nt) {
                const uint32_t bb1 = (ks == 15) ? mb[nt] : v[nt];
                mma16(acc[0][nt], a[cur][0], v[nt + 1], bb1);
                mma16(acc[1][nt], a[cur][1], v[nt + 1], bb1);
            }
            if (ks < 15) {
#pragma unroll
                for (int j = 8; j >= 2; --j) v[j] = v[j - 2];
                v[1] = nv1; v[0] = nv0;
                ra0 += 32; ra1 += 32; rb += 64;
            }
        }

        __syncthreads();

        const float* gs  = gext + (l - 1) * 260;
        const float* lws = lw_s + (l - 1) * NMODES;
        const bool last = (l == 4);
#pragma unroll
        for (int mt = 0; mt < 2; ++mt)
#pragma unroll
            for (int half = 0; half < 2; ++half) {
                int r = wm * 32 + mt * 16 + half * 8 + lg;
                float x0 = x_s[r * 4 + 0];
                float x1 = x_s[r * 4 + 1];
                float x2 = x_s[r * 4 + 2];
#pragma unroll
                for (int nt = 0; nt < 8; ++nt) {
                    int n = wn * 64 + nt * 8 + 2 * tig;
                    const int widx = r * HW + wn * 32 + nt * 4 + tig;
                    uint32_t hraw = hw[widx];
                    __half2 ho = *(const __half2*)&hraw;
                    float2 lw2 = *(const float2*)(lws + n);
                    // g_ext[n..n+3] = g[n-2], g[n-1], g[n], g[n+1]
                    float2 p = *(const float2*)(gs + n);
                    float2 q = *(const float2*)(gs + n + 2);
                    float v0 = acc[mt][nt][half * 2 + 0]
                             + x0 * q.x + x1 * p.y + x2 * p.x
                             + __low2float(ho) * lw2.x;
                    float v1 = acc[mt][nt][half * 2 + 1]
                             + x0 * q.y + x1 * q.x + x2 * p.y
                             + __high2float(ho) * lw2.y;
                    v0 = fmaxf(v0, 0.0f);
                    v1 = fmaxf(v1, 0.0f);
                    if (!last) {
                        __half2 h2 = __floats2half2_rn(v0, v1);
                        hw[widx] = *(const uint32_t*)&h2;
                    } else {
                        float2 w2v = *(const float2*)(w2_s + n);
                        dsum[mt * 2 + half] += v0 * w2v.x + v1 * w2v.y;
                    }
                }
            }
        if (!last) __syncthreads();
    }

    // ---------------- decoder reduction ----------------
#pragma unroll
    for (int s = 0; s < 4; ++s) {
        dsum[s] += __shfl_xor_sync(0xffffffffu, dsum[s], 1);
        dsum[s] += __shfl_xor_sync(0xffffffffu, dsum[s], 2);
    }
    if (tig == 0) {
#pragma unroll
        for (int s = 0; s < 4; ++s) {
            int mt = s >> 1, half = s & 1;
            int r = wm * 32 + mt * 16 + half * 8 + lg;
            dec[r * 4 + wn] = dsum[s];
        }
    }
    __syncthreads();
    if (tid < MROWS) {
        const float* d = dec + tid * 4;
        out[row0 + tid] = d[0] + d[1] + d[2] + d[3] + b2v[0];
    }
}

// ---------------------------------------------------------------------------
extern "C" void kernel_launch(void* const* d_in, const int* in_sizes, int n_in,
                              void* d_out, int out_size) {
    const float* mu = (const float*)d_in[0];
    const float* x  = (const float*)d_in[1];
    const float* W1 = (const float*)d_in[2];
    const float* b1 = (const float*)d_in[3];
    const float* fw = (const float*)d_in[4];
    const float* lw = (const float*)d_in[5];
    const float* W2 = (const float*)d_in[6];
    const float* b2 = (const float*)d_in[7];
    float* out = (float*)d_out;

    const int B = in_sizes[0] / 64;
    const int nblocks = B / MROWS;

    build_g<<<NLAYERS, NMODES>>>(fw);
    build_t2<<<dim3(NLAYERS, 2), 256>>>();
    build_w1sw<<<NMODES, 64>>>(W1);

    cudaFuncSetAttribute(fno_main, cudaFuncAttributeMaxDynamicSharedMemorySize, SMEM_TOTAL);
    fno_main<<<nblocks, NTHREADS, SMEM_TOTAL>>>(mu, x, b1, lw, W2, b2, out);
}

// round 11
// speedup vs baseline: 1.2454x; 1.0796x over previous
#include <cuda_runtime.h>
#include <cuda_fp16.h>
#include <cstdint>

// ---------------------------------------------------------------------------
// FNO on sm_103a. Circulant Fourier layers via a 2KB reversed-g pair table:
// B[k][n] = g[(n-k-3) mod 256]. The UNCROPPED circulant at k=253..255 equals
// the x-term coefficients (g[n], g[n-1], g[n-2]), so x0,x1,x2 live in h's
// k-columns 253..255 and the MMA computes conv + x-term together — no crop
// mask, no epilogue x-term. True h[253..255] (for the lw diagonal) lives in
// a 1KB side array, special-cased in 2 of 32 epilogue lanes.
//   h0 = relu(mu @ W1 + b1)           (W1 via one-shot cp.async, ldsm path)
//   h  = relu(circ_g([h|x]) + h*lw)   l=0..3
//   out = h @ W2 + b2                 (fused into stage-4 epilogue, fp32)
// 256 threads, 64 rows/CTA, 82KB SMEM -> 2 CTAs/SM. No weight streaming.
// ---------------------------------------------------------------------------

#define NMODES 256
#define NLAYERS 4
#define MROWS 64
#define NTHREADS 256
#define HW 132                              // h row stride in 32-bit words
#define H_BYTES (MROWS * HW * 4)            // 33792
#define W1_OFF  H_BYTES                     // 32KB swizzled W1 image
#define T2_OFF  (W1_OFF + 32768)            // 66560: 4 x 2048B pair tables
#define B1_OFF  (T2_OFF + NLAYERS * 2048)   // 74752: b1 (fp32)
#define LW_OFF  (B1_OFF + NMODES * 4)       // 75776: 4x lw (fp32)
#define XS_OFF  (LW_OFF + NLAYERS * NMODES * 4) // 79872
#define W2S_OFF (XS_OFF + MROWS * 4 * 4)    // 80896
#define DEC_OFF (W2S_OFF + NMODES * 4)      // 81920
#define HS_OFF  (DEC_OFF + MROWS * 4 * 4)   // 82944: h[253..255] side (fp32)
#define SMEM_TOTAL (HS_OFF + MROWS * 4 * 4) // 83968

__device__ float g_dev[NLAYERS * NMODES];
__device__ __align__(16) uint32_t t2_dev[NLAYERS * 512]; // half2 pair tables
__device__ __align__(16) __half w1sw_dev[NMODES * 64];   // swizzled W1^T image

__device__ __forceinline__ uint32_t smem_u32(const void* p) {
    uint32_t a;
    asm("{ .reg .u64 t; cvta.to.shared.u64 t, %1; cvt.u32.u64 %0, t; }" : "=r"(a) : "l"(p));
    return a;
}

#define CP_ASYNC16(dst, src) \
    asm volatile("cp.async.cg.shared.global [%0], [%1], 16;" :: "r"(dst), "l"(src) : "memory")
#define CP_COMMIT() asm volatile("cp.async.commit_group;" ::: "memory")
#define CP_WAIT0()  asm volatile("cp.async.wait_group 0;" ::: "memory")

#define LDS_B(dst, base, imm) \
    asm volatile("ld.shared.b32 %0, [%1+%2];" : "=r"(dst) : "r"(base), "n"(imm))

__device__ __forceinline__ void mma16(float* c, const uint32_t* a, uint32_t b0, uint32_t b1) {
    asm volatile(
        "mma.sync.aligned.m16n8k16.row.col.f32.f16.f16.f32 "
        "{%0,%1,%2,%3}, {%4,%5,%6,%7}, {%8,%9}, {%0,%1,%2,%3};\n"
        : "+f"(c[0]), "+f"(c[1]), "+f"(c[2]), "+f"(c[3])
        : "r"(a[0]), "r"(a[1]), "r"(a[2]), "r"(a[3]), "r"(b0), "r"(b1));
}

__device__ __forceinline__ void ldsm_x4(uint32_t& r0, uint32_t& r1, uint32_t& r2, uint32_t& r3,
                                        uint32_t addr) {
    asm volatile("ldmatrix.sync.aligned.m8n8.x4.shared.b16 {%0,%1,%2,%3}, [%4];"
                 : "=r"(r0), "=r"(r1), "=r"(r2), "=r"(r3) : "r"(addr));
}

// ---------------- preludes ----------------
__global__ void build_g(const float* __restrict__ fw) {
    int l = blockIdx.x, n = threadIdx.x;
    const float* f = fw + l * 129;
    float acc = f[0] + ((n & 1) ? -f[128] : f[128]);
    float nn = (float)n;
#pragma unroll 4
    for (int k = 1; k < 128; ++k)
        acc += 2.0f * f[k] * cospif((float)k * nn * (1.0f / 128.0f));
    g_dev[l * NMODES + n] = acc * (1.0f / 256.0f);
}

// pair table: t2[l][i] = half2{ g_l[(252-i)&255], g_l[(251-i)&255] }, i<511
__global__ void build_t2() {
    int l = blockIdx.x, i = threadIdx.x + 256 * blockIdx.y;
    if (i >= 512) return;
    uint32_t v = 0;
    if (i < 511) {
        __half lo = __float2half_rn(g_dev[l * NMODES + ((252 - i) & 255)]);
        __half hi = __float2half_rn(g_dev[l * NMODES + ((251 - i) & 255)]);
        __half2 h2 = __halves2half2(lo, hi);
        v = *(const uint32_t*)&h2;
    }
    t2_dev[l * 512 + i] = v;
}

// swizzled W1^T image: element (n, pos*8+jj) <- W1[k=(pos^(n&7))*8+jj][n]
__global__ void build_w1sw(const float* __restrict__ W1) {
    int n = blockIdx.x, j = threadIdx.x;
    int pos = j >> 3, jj = j & 7;
    int k = ((pos ^ (n & 7)) << 3) + jj;
    w1sw_dev[n * 64 + j] = __float2half_rn(W1[k * NMODES + n]);
}

// ---------------- main ----------------
__global__ __launch_bounds__(NTHREADS, 2)
void fno_main(const float* __restrict__ mu, const float* __restrict__ xin,
              const float* __restrict__ b1, const float* __restrict__ lw,
              const float* __restrict__ W2, const float* __restrict__ b2v,
              float* __restrict__ out) {
    extern __shared__ __align__(16) char smem[];
    const uint32_t sb = smem_u32(smem);
    uint32_t* hw   = (uint32_t*)smem;
    uint32_t* t2s  = (uint32_t*)(smem + T2_OFF);
    float* b1_s    = (float*)(smem + B1_OFF);
    float* lw_s    = (float*)(smem + LW_OFF);
    float* x_s     = (float*)(smem + XS_OFF);
    float* w2_s    = (float*)(smem + W2S_OFF);
    float* dec     = (float*)(smem + DEC_OFF);
    float* hside   = (float*)(smem + HS_OFF);

    const int tid  = threadIdx.x;
    const int lane = tid & 31;
    const int warp = tid >> 5;
    const int lg   = lane >> 2;   // 0..7
    const int tig  = lane & 3;    // 0..3
    const int wm   = warp >> 2;   // 0..1
    const int wn   = warp & 3;    // 0..3
    const size_t row0 = (size_t)blockIdx.x * MROWS;

    // one-shot W1 image copy
    {
        const char* src = (const char*)w1sw_dev;
#pragma unroll
        for (int i = 0; i < 8; ++i) {
            int idx = tid + i * NTHREADS;
            CP_ASYNC16(sb + W1_OFF + idx * 16, src + idx * 16);
        }
        CP_COMMIT();
    }

    // tables & small data
    for (int i = tid; i < NLAYERS * 512; i += NTHREADS) t2s[i] = t2_dev[i];
    if (tid < NMODES) b1_s[tid] = b1[tid];
    for (int i = tid; i < NLAYERS * NMODES; i += NTHREADS) lw_s[i] = lw[i];
    for (int i = tid; i < MROWS * 3; i += NTHREADS) {
        int r = i / 3, c = i - r * 3;
        x_s[r * 4 + c] = xin[(row0 + r) * 3 + c];
    }
    if (tid < NMODES) w2_s[tid] = W2[tid];

    // mu -> h fp16 words [r][0..31]
    for (int i = tid; i < MROWS * 32; i += NTHREADS) {
        int r = i >> 5, w = i & 31;
        float2 v = ((const float2*)(mu + (row0 + r) * 64))[w];
        __half2 h2 = __floats2half2_rn(v.x, v.y);
        hw[r * HW + w] = *(const uint32_t*)&h2;
    }

    // A ldsm lane bases
    const int a_row = lane & 15;
    const uint32_t a_koff = (uint32_t)((lane >> 4) << 4);
    uint32_t a_base[2];
#pragma unroll
    for (int mt = 0; mt < 2; ++mt)
        a_base[mt] = sb + (wm * 32 + mt * 16 + a_row) * (HW * 4) + a_koff;

    // W1 (swizzled) ldsm lane bases
    const int b_nloc = ((lane & 16) >> 1) + (lane & 7);
    const int hi = (lane >> 3) & 1;
    uint32_t w1_off[4];
    int bx[4];
#pragma unroll
    for (int ntp = 0; ntp < 4; ++ntp) {
        int n = wn * 64 + ntp * 16 + b_nloc;
        w1_off[ntp] = (uint32_t)(n << 7);
        bx[ntp] = n & 7;
    }

    // circulant-table per-lane base: addr(ks,nt,b) = rb + 64*ks + (256 - 32*(nt+1-b))
    const uint32_t rb0 = sb + T2_OFF + 1020u + 8u * tig - 4u * lg - 256u * wn - 224u;

    // epilogue special lanes (n in 252..255): wn==3, nt==7, tig>=2
    const bool sp_warp = (wn == 3);

    float acc[2][8][4];
#define ZERO_ACC()                                   \
    _Pragma("unroll") for (int mt = 0; mt < 2; ++mt) \
    _Pragma("unroll") for (int nt = 0; nt < 8; ++nt) \
    _Pragma("unroll") for (int j = 0; j < 4; ++j) acc[mt][nt][j] = 0.0f;

    CP_WAIT0();
    __syncthreads();

    // ---------------- encoder gemm (K=64, W1 image via ldsm) ----------------
    ZERO_ACC();
    {
        const uint32_t wbase = sb + W1_OFF;
#pragma unroll
        for (int ks = 0; ks < 4; ++ks) {
            uint32_t a[2][4];
            ldsm_x4(a[0][0], a[0][1], a[0][2], a[0][3], a_base[0] + ks * 32);
            ldsm_x4(a[1][0], a[1][1], a[1][2], a[1][3], a_base[1] + ks * 32);
            const int seg = ks * 2 + hi;
#pragma unroll
            for (int ntp = 0; ntp < 4; ++ntp) {
                uint32_t b0, b1r, b2, b3;
                ldsm_x4(b0, b1r, b2, b3,
                        wbase + w1_off[ntp] + (uint32_t)(((seg ^ bx[ntp]) & 7) << 4));
                mma16(acc[0][2 * ntp],     a[0], b0, b1r);
                mma16(acc[1][2 * ntp],     a[1], b0, b1r);
                mma16(acc[0][2 * ntp + 1], a[0], b2, b3);
                mma16(acc[1][2 * ntp + 1], a[1], b2, b3);
            }
        }
    }
    __syncthreads();
    // encoder epilogue: relu(acc + b1) -> h; k-cols 253..255 get x, true h -> hside
#pragma unroll
    for (int mt = 0; mt < 2; ++mt)
#pragma unroll
        for (int half = 0; half < 2; ++half) {
            int r = wm * 32 + mt * 16 + half * 8 + lg;
#pragma unroll
            for (int nt = 0; nt < 8; ++nt) {
                int n = wn * 64 + nt * 8 + 2 * tig;
                float2 bv = *(const float2*)(b1_s + n);
                float v0 = fmaxf(acc[mt][nt][half * 2 + 0] + bv.x, 0.0f);
                float v1 = fmaxf(acc[mt][nt][half * 2 + 1] + bv.y, 0.0f);
                if (sp_warp && nt == 7 && tig >= 2) {
                    if (tig == 2) { hside[r * 4 + 0] = v1; v1 = x_s[r * 4 + 0]; }
                    else { hside[r * 4 + 1] = v0; hside[r * 4 + 2] = v1;
                           v0 = x_s[r * 4 + 1]; v1 = x_s[r * 4 + 2]; }
                }
                __half2 h2 = __floats2half2_rn(v0, v1);
                hw[r * HW + wn * 32 + nt * 4 + tig] = *(const uint32_t*)&h2;
            }
        }
    __syncthreads();

    // ---------------- Fourier stages ----------------
    float dsum[4];
#pragma unroll
    for (int s = 0; s < 4; ++s) dsum[s] = 0.0f;

#pragma unroll 1
    for (int l = 1; l <= 4; ++l) {
        ZERO_ACC();
        uint32_t rb = rb0 + (uint32_t)((l - 1) * 2048);
        uint32_t ra0 = a_base[0], ra1 = a_base[1];

        // sliding window: v[j] = table[rb + 256 - 32j]; b1[nt]=v[nt], b0[nt]=v[nt+1]
        uint32_t v[9];
        uint32_t a[2][2][4];
        ldsm_x4(a[0][0][0], a[0][0][1], a[0][0][2], a[0][0][3], ra0);
        ldsm_x4(a[0][1][0], a[0][1][1], a[0][1][2], a[0][1][3], ra1);
        LDS_B(v[0], rb, 256); LDS_B(v[1], rb, 224); LDS_B(v[2], rb, 192);
        LDS_B(v[3], rb, 160); LDS_B(v[4], rb, 128); LDS_B(v[5], rb,  96);
        LDS_B(v[6], rb,  64); LDS_B(v[7], rb,  32); LDS_B(v[8], rb,   0);

#pragma unroll
        for (int ks = 0; ks < 16; ++ks) {
            const int cur = ks & 1, nxt = cur ^ 1;
            uint32_t nv0 = 0, nv1 = 0;
            if (ks < 15) {
                ldsm_x4(a[nxt][0][0], a[nxt][0][1], a[nxt][0][2], a[nxt][0][3], ra0 + 32);
                ldsm_x4(a[nxt][1][0], a[nxt][1][1], a[nxt][1][2], a[nxt][1][3], ra1 + 32);
                LDS_B(nv0, rb, 320);   // next slice v[0]
                LDS_B(nv1, rb, 288);   // next slice v[1]
            }
#pragma unroll
            for (int nt = 0; nt < 8; ++nt) {
                mma16(acc[0][nt], a[cur][0], v[nt + 1], v[nt]);
                mma16(acc[1][nt], a[cur][1], v[nt + 1], v[nt]);
            }
            if (ks < 15) {
#pragma unroll
                for (int j = 8; j >= 2; --j) v[j] = v[j - 2];
                v[1] = nv1; v[0] = nv0;
                ra0 += 32; ra1 += 32; rb += 64;
            }
        }

        __syncthreads();

        const float* lws = lw_s + (l - 1) * NMODES;
        const bool last = (l == 4);
#pragma unroll
        for (int mt = 0; mt < 2; ++mt)
#pragma unroll
            for (int half = 0; half < 2; ++half) {
                int r = wm * 32 + mt * 16 + half * 8 + lg;
#pragma unroll
                for (int nt = 0; nt < 8; ++nt) {
                    int n = wn * 64 + nt * 8 + 2 * tig;
                    const int widx = r * HW + wn * 32 + nt * 4 + tig;
                    uint32_t hraw = hw[widx];
                    __half2 ho = *(const __half2*)&hraw;
                    float h0f = __low2float(ho);
                    float h1f = __high2float(ho);
                    const bool sp = sp_warp && nt == 7 && tig >= 2;
                    if (sp) {
                        if (tig == 2) h1f = hside[r * 4 + 0];
                        else { h0f = hside[r * 4 + 1]; h1f = hside[r * 4 + 2]; }
                    }
                    float2 lw2 = *(const float2*)(lws + n);
                    float v0 = fmaxf(acc[mt][nt][half * 2 + 0] + h0f * lw2.x, 0.0f);
                    float v1 = fmaxf(acc[mt][nt][half * 2 + 1] + h1f * lw2.y, 0.0f);
                    if (!last) {
                        if (sp) {
                            if (tig == 2) { hside[r * 4 + 0] = v1; v1 = x_s[r * 4 + 0]; }
                            else { hside[r * 4 + 1] = v0; hside[r * 4 + 2] = v1;
                                   v0 = x_s[r * 4 + 1]; v1 = x_s[r * 4 + 2]; }
                        }
                        __half2 h2 = __floats2half2_rn(v0, v1);
                        hw[widx] = *(const uint32_t*)&h2;
                    } else {
                        float2 w2v = *(const float2*)(w2_s + n);
                        dsum[mt * 2 + half] += v0 * w2v.x + v1 * w2v.y;
                    }
                }
            }
        if (!last) __syncthreads();
    }

    // ---------------- decoder reduction ----------------
#pragma unroll
    for (int s = 0; s < 4; ++s) {
        dsum[s] += __shfl_xor_sync(0xffffffffu, dsum[s], 1);
        dsum[s] += __shfl_xor_sync(0xffffffffu, dsum[s], 2);
    }
    if (tig == 0) {
#pragma unroll
        for (int s = 0; s < 4; ++s) {
            int mt = s >> 1, half = s & 1;
            int r = wm * 32 + mt * 16 + half * 8 + lg;
            dec[r * 4 + wn] = dsum[s];
        }
    }
    __syncthreads();
    if (tid < MROWS) {
        const float* d = dec + tid * 4;
        out[row0 + tid] = d[0] + d[1] + d[2] + d[3] + b2v[0];
    }
}

// ---------------------------------------------------------------------------
extern "C" void kernel_launch(void* const* d_in, const int* in_sizes, int n_in,
                              void* d_out, int out_size) {
    const float* mu = (const float*)d_in[0];
    const float* x  = (const float*)d_in[1];
    const float* W1 = (const float*)d_in[2];
    const float* b1 = (const float*)d_in[3];
    const float* fw = (const float*)d_in[4];
    const float* lw = (const float*)d_in[5];
    const float* W2 = (const float*)d_in[6];
    const float* b2 = (const float*)d_in[7];
    float* out = (float*)d_out;

    const int B = in_sizes[0] / 64;
    const int nblocks = B / MROWS;

    build_g<<<NLAYERS, NMODES>>>(fw);
    build_t2<<<dim3(NLAYERS, 2), 256>>>();
    build_w1sw<<<NMODES, 64>>>(W1);

    cudaFuncSetAttribute(fno_main, cudaFuncAttributeMaxDynamicSharedMemorySize, SMEM_TOTAL);
    fno_main<<<nblocks, NTHREADS, SMEM_TOTAL>>>(mu, x, b1, lw, W2, b2, out);
}